// round 6
// baseline (speedup 1.0000x reference)
#include <cuda_runtime.h>
#include <cstdint>

// LSTM T=8192, H=128. 2 CTAs x 512 threads (cluster), syncless inner loop.
// Thread (e,gate,hf): lane bits l=[e_lo(2)|gate(2)|hf(1)], warp w gives e_hi.
// Each thread: 64 weights = cols [q*64+hf*32,+32) (local) + [peer*64+hf*32,+32).
// Combine: shfl.xor(1) half-sum, then xor(2)/(4)/(6) for gates f/g/o.
// h exchange: producers st.async to both CTAs; barL (local, 256B) + barR
// (remote, 256B) ping-pong tx-barriers; no __syncthreads in the loop.

#define HD 128
#define TPC 512
#define TXQ 256   // 64 floats

typedef unsigned long long u64;

__device__ __forceinline__ u64 ffma2(u64 a, u64 b, u64 c) {
    u64 d;
    asm("fma.rn.f32x2 %0, %1, %2, %3;" : "=l"(d) : "l"(a), "l"(b), "l"(c));
    return d;
}
__device__ __forceinline__ u64 pack2(float lo, float hi) {
    u64 r;
    asm("mov.b64 %0, {%1, %2};" : "=l"(r) : "f"(lo), "f"(hi));
    return r;
}
__device__ __forceinline__ void unpack2(u64 v, float& lo, float& hi) {
    asm("mov.b64 {%0, %1}, %2;" : "=f"(lo), "=f"(hi) : "l"(v));
}
__device__ __forceinline__ float sigm(float x) {
    x = fminf(fmaxf(x, -30.f), 30.f);
    return __fdividef(1.f, 1.f + __expf(-x));
}
__device__ __forceinline__ float tanh_(float x) {
    x = fminf(fmaxf(x, -15.f), 15.f);
    float e = __expf(-2.f * x);
    return __fdividef(1.f - e, 1.f + e);
}
__device__ __forceinline__ uint32_t smem_u32(const void* p) {
    return (uint32_t)__cvta_generic_to_shared(p);
}
__device__ __forceinline__ uint32_t mapa_u32(uint32_t addr, uint32_t rank) {
    uint32_t r;
    asm("mapa.shared::cluster.u32 %0, %1, %2;" : "=r"(r) : "r"(addr), "r"(rank));
    return r;
}
__device__ __forceinline__ void mbar_init(uint32_t a, uint32_t cnt) {
    asm volatile("mbarrier.init.shared.b64 [%0], %1;" :: "r"(a), "r"(cnt) : "memory");
}
__device__ __forceinline__ void mbar_arrive(uint32_t a) {
    asm volatile("mbarrier.arrive.shared.b64 _, [%0];" :: "r"(a) : "memory");
}
__device__ __forceinline__ void mbar_arrive_expect_tx(uint32_t a, uint32_t tx) {
    asm volatile("mbarrier.arrive.expect_tx.shared.b64 _, [%0], %1;"
                 :: "r"(a), "r"(tx) : "memory");
}
__device__ __forceinline__ void st_async_f32(uint32_t raddr, float v, uint32_t rmbar) {
    asm volatile(
        "st.async.shared::cluster.mbarrier::complete_tx::bytes.f32 [%0], %1, [%2];"
        :: "r"(raddr), "f"(v), "r"(rmbar) : "memory");
}
__device__ __forceinline__ void mbar_wait(uint32_t a, uint32_t parity) {
    asm volatile(
        "{\n\t"
        ".reg .pred P;\n\t"
        "WL_%=:\n\t"
        "mbarrier.try_wait.parity.acquire.cluster.shared::cta.b64 P, [%0], %1;\n\t"
        "@P bra WD_%=;\n\t"
        "bra WL_%=;\n\t"
        "WD_%=:\n\t"
        "}" :: "r"(a), "r"(parity) : "memory");
}
__device__ __forceinline__ void cluster_sync() {
    asm volatile("barrier.cluster.arrive.aligned;" ::: "memory");
    asm volatile("barrier.cluster.wait.aligned;" ::: "memory");
}

extern "C" __global__ void __launch_bounds__(TPC, 1) __cluster_dims__(2, 1, 1)
lstm_k(const float* __restrict__ x,
       const float* __restrict__ W_ih,
       const float* __restrict__ W_hh,
       const float* __restrict__ b_ih,
       const float* __restrict__ b_hh,
       const float* __restrict__ W_lin,
       const float* __restrict__ b_lin,
       const float* __restrict__ h0,
       const float* __restrict__ c0,
       float* __restrict__ out,
       int T) {
    __shared__ __align__(16) float hs[2][HD];
    __shared__ float red[4];
    __shared__ __align__(8) u64 barL[2];
    __shared__ __align__(8) u64 barR[2];

    const int r = threadIdx.x;
    uint32_t rank;
    asm("mov.u32 %0, %%cluster_ctarank;" : "=r"(rank));
    const int q = (int)rank;
    const int peer = 1 - q;

    const int l    = r & 31;
    const int w    = r >> 5;
    const int e    = w * 4 + (l >> 3);     // element 0..63
    const int gate = (l >> 1) & 3;         // i,f,g,o
    const int hf   = l & 1;                // column half
    const int row  = gate * HD + q * 64 + e;
    const int j    = q * 64 + e;           // global h index of this element
    const bool prod = ((l & 7) == 0);      // gate 0, hf 0

    const float in_sc  = (gate == 2) ? 2.f : 1.f;
    const float out_sc = (gate == 2) ? 2.f : 1.f;
    const float out_b  = (gate == 2) ? -1.f : 0.f;

    const uint32_t bl0 = smem_u32(&barL[0]), bl1 = smem_u32(&barL[1]);
    const uint32_t br0 = smem_u32(&barR[0]), br1 = smem_u32(&barR[1]);
    const uint32_t hsb = smem_u32(&hs[0][0]);

    // self (loopback) and peer cluster addresses
    const uint32_t self_hs = mapa_u32(hsb, (uint32_t)q);
    const uint32_t self_bl[2] = { mapa_u32(bl0, (uint32_t)q), mapa_u32(bl1, (uint32_t)q) };
    const uint32_t peer_hs = mapa_u32(hsb, (uint32_t)peer);
    const uint32_t peer_br[2] = { mapa_u32(br0, (uint32_t)peer), mapa_u32(br1, (uint32_t)peer) };
    const uint32_t mbl[2] = { bl0, bl1 };
    const uint32_t mbr[2] = { br0, br1 };

    if (r == 0) {
        mbar_init(bl0, 1); mbar_init(bl1, 1);
        mbar_init(br0, 1); mbar_init(br1, 1);
    }
    __syncthreads();
    if (r == 0) {
        mbar_arrive(bl0);                 // phase 0 completes: step 0 passes free
        mbar_arrive(br0);
        mbar_arrive_expect_tx(bl1, TXQ);  // armed for step 1's local quarter
        mbar_arrive_expect_tx(br1, TXQ);  // armed for step 1's remote quarter
    }

    if (r < HD) hs[0][r] = h0[r];
    float c = prod ? c0[j] : 0.f;

    // weights: 16 u64 local cols, 16 u64 remote cols
    const float wih  = W_ih[row];
    const float bsum = b_ih[row] + b_hh[row];
    u64 wloc[16], wrem[16];
    {
        const u64* wrow = (const u64*)(W_hh + (size_t)row * HD);
        const int lo = q * 32 + hf * 16;
        const int ro = peer * 32 + hf * 16;
        #pragma unroll
        for (int k = 0; k < 16; ++k) wloc[k] = wrow[lo + k];
        #pragma unroll
        for (int k = 0; k < 16; ++k) wrem[k] = wrow[ro + k];
    }
    __syncthreads();
    cluster_sync();    // all barriers init/armed + hs[0] visible before any st.async

    const int lchunk = q * 16 + hf * 8;     // ull2 index of local 32-col block
    const int rchunk = peer * 16 + hf * 8;
    float xt = __ldg(&x[0]);

    for (int t = 0; t < T; ++t) {
        const int b  = t & 1;
        const int nb = b ^ 1;
        const uint32_t parity = (uint32_t)((t >> 1) & 1);

        int tn = t + 1; tn = (tn < T) ? tn : t;
        const float xnext = __ldg(&x[tn]);

        // wait for local quarter of hs[b] (loopback st.async from step t-1)
        mbar_wait(mbl[b], parity);

        u64 a0 = hf ? 0ull : pack2(fmaf(wih, xt, bsum), 0.f);
        u64 a1 = 0ull, a2 = 0ull, a3 = 0ull;

        const ulonglong2* hv2 = (const ulonglong2*)(&hs[b][0]);

        #pragma unroll
        for (int k = 0; k < 8; k += 2) {
            ulonglong2 u = hv2[lchunk + k];
            ulonglong2 v = hv2[lchunk + k + 1];
            a0 = ffma2(wloc[2 * k + 0], u.x, a0);
            a1 = ffma2(wloc[2 * k + 1], u.y, a1);
            a2 = ffma2(wloc[2 * k + 2], v.x, a2);
            a3 = ffma2(wloc[2 * k + 3], v.y, a3);
        }

        mbar_wait(mbr[b], parity);              // peer quarter landed
        if (r == 0) {                            // re-arm pair b for step t+2
            mbar_arrive_expect_tx(mbl[b], TXQ);
            mbar_arrive_expect_tx(mbr[b], TXQ);
        }

        #pragma unroll
        for (int k = 0; k < 8; k += 2) {
            ulonglong2 u = hv2[rchunk + k];
            ulonglong2 v = hv2[rchunk + k + 1];
            a0 = ffma2(wrem[2 * k + 0], u.x, a0);
            a1 = ffma2(wrem[2 * k + 1], u.y, a1);
            a2 = ffma2(wrem[2 * k + 2], v.x, a2);
            a3 = ffma2(wrem[2 * k + 3], v.y, a3);
        }

        float s0, s1, s2, s3, s4, s5, s6, s7;
        unpack2(a0, s0, s1);
        unpack2(a1, s2, s3);
        unpack2(a2, s4, s5);
        unpack2(a3, s6, s7);
        float gpre = ((s0 + s1) + (s2 + s3)) + ((s4 + s5) + (s6 + s7));

        gpre += __shfl_xor_sync(0xFFFFFFFFu, gpre, 1);   // combine column halves

        const float act = fmaf(out_sc, sigm(in_sc * gpre), out_b);

        const float fv = __shfl_xor_sync(0xFFFFFFFFu, act, 2);
        const float gv = __shfl_xor_sync(0xFFFFFFFFu, act, 4);
        const float ov = __shfl_xor_sync(0xFFFFFFFFu, act, 6);

        if (prod) {
            c = fmaf(fv, c, act * gv);           // act == i on producer lane
            const float hnew = ov * tanh_(c);
            const uint32_t off = (uint32_t)((nb * HD + j) * 4);
            st_async_f32(peer_hs + off, hnew, peer_br[nb]);  // remote first
            st_async_f32(self_hs + off, hnew, self_bl[nb]);  // local loopback
        }
        xt = xnext;
    }

    // CTA0 consumes final h
    if (q == 0) {
        const int bf = T & 1;
        const uint32_t pf = (uint32_t)((T >> 1) & 1);
        mbar_wait(mbl[bf], pf);
        mbar_wait(mbr[bf], pf);
        if (r < HD) {
            float v = hs[bf][r] * W_lin[r];
            #pragma unroll
            for (int o = 16; o > 0; o >>= 1)
                v += __shfl_down_sync(0xFFFFFFFFu, v, o);
            if ((r & 31) == 0) red[r >> 5] = v;
        }
        __syncthreads();
        if (r == 0) out[0] = red[0] + red[1] + red[2] + red[3] + b_lin[0];
    }
    cluster_sync();   // peer must outlive final consumption
}

extern "C" void kernel_launch(void* const* d_in, const int* in_sizes, int n_in,
                              void* d_out, int out_size) {
    const float* x     = (const float*)d_in[0];
    const float* W_ih  = (const float*)d_in[1];
    const float* W_hh  = (const float*)d_in[2];
    const float* b_ih  = (const float*)d_in[3];
    const float* b_hh  = (const float*)d_in[4];
    const float* W_lin = (const float*)d_in[5];
    const float* b_lin = (const float*)d_in[6];
    const float* h0    = (const float*)d_in[7];
    const float* c0    = (const float*)d_in[8];
    float* out = (float*)d_out;

    const int T = in_sizes[0];

    lstm_k<<<2, TPC>>>(x, W_ih, W_hh, b_ih, b_hh,
                       W_lin, b_lin, h0, c0, out, T);
}

// round 7
// speedup vs baseline: 1.9763x; 1.9763x over previous
#include <cuda_runtime.h>
#include <cstdint>

// LSTM T=8192, H=128. Cluster of 2 CTAs x 256 threads (R4 skeleton).
// All W_hh in registers. Interleaved lanes: gate = r&3, element m = r>>2.
// Gate combine via shfl.bfly; remote h via st.async + tx mbarriers;
// local h via smem + one __syncthreads. NEW vs R4: MUFU tanh.approx
// activations (sigma(x) = 0.5*tanh(0.5x)+0.5) and f32x2 packed adds
// for the accumulator combine — both on the serial recurrence chain.

#define HD 128
#define TPC 256
#define HALF 64

typedef unsigned long long u64;

__device__ __forceinline__ u64 ffma2(u64 a, u64 b, u64 c) {
    u64 d;
    asm("fma.rn.f32x2 %0, %1, %2, %3;" : "=l"(d) : "l"(a), "l"(b), "l"(c));
    return d;
}
__device__ __forceinline__ u64 addf2(u64 a, u64 b) {
    u64 d;
    asm("add.rn.f32x2 %0, %1, %2;" : "=l"(d) : "l"(a), "l"(b));
    return d;
}
__device__ __forceinline__ u64 pack2(float lo, float hi) {
    u64 r;
    asm("mov.b64 %0, {%1, %2};" : "=l"(r) : "f"(lo), "f"(hi));
    return r;
}
__device__ __forceinline__ void unpack2(u64 v, float& lo, float& hi) {
    asm("mov.b64 {%0, %1}, %2;" : "=f"(lo), "=f"(hi) : "l"(v));
}
__device__ __forceinline__ float tanhfast(float x) {   // MUFU.TANH
    float y;
    asm("tanh.approx.f32 %0, %1;" : "=f"(y) : "f"(x));
    return y;
}
__device__ __forceinline__ uint32_t smem_u32(const void* p) {
    return (uint32_t)__cvta_generic_to_shared(p);
}
__device__ __forceinline__ uint32_t mapa_u32(uint32_t addr, uint32_t rank) {
    uint32_t r;
    asm("mapa.shared::cluster.u32 %0, %1, %2;" : "=r"(r) : "r"(addr), "r"(rank));
    return r;
}
__device__ __forceinline__ void mbar_init(uint32_t a, uint32_t cnt) {
    asm volatile("mbarrier.init.shared.b64 [%0], %1;" :: "r"(a), "r"(cnt) : "memory");
}
__device__ __forceinline__ void mbar_arrive(uint32_t a) {
    asm volatile("mbarrier.arrive.shared.b64 _, [%0];" :: "r"(a) : "memory");
}
__device__ __forceinline__ void mbar_arrive_expect_tx(uint32_t a, uint32_t tx) {
    asm volatile("mbarrier.arrive.expect_tx.shared.b64 _, [%0], %1;"
                 :: "r"(a), "r"(tx) : "memory");
}
__device__ __forceinline__ void st_async_f32(uint32_t raddr, float v, uint32_t rmbar) {
    asm volatile(
        "st.async.shared::cluster.mbarrier::complete_tx::bytes.f32 [%0], %1, [%2];"
        :: "r"(raddr), "f"(v), "r"(rmbar) : "memory");
}
__device__ __forceinline__ void mbar_wait(uint32_t a, uint32_t parity) {
    asm volatile(
        "{\n\t"
        ".reg .pred P;\n\t"
        "WL_%=:\n\t"
        "mbarrier.try_wait.parity.acquire.cluster.shared::cta.b64 P, [%0], %1;\n\t"
        "@P bra WD_%=;\n\t"
        "bra WL_%=;\n\t"
        "WD_%=:\n\t"
        "}" :: "r"(a), "r"(parity) : "memory");
}
__device__ __forceinline__ void cluster_sync() {
    asm volatile("barrier.cluster.arrive.aligned;" ::: "memory");
    asm volatile("barrier.cluster.wait.aligned;" ::: "memory");
}

extern "C" __global__ void __launch_bounds__(TPC, 1) __cluster_dims__(2, 1, 1)
lstm_cluster_kernel(const float* __restrict__ x,
                    const float* __restrict__ W_ih,
                    const float* __restrict__ W_hh,
                    const float* __restrict__ b_ih,
                    const float* __restrict__ b_hh,
                    const float* __restrict__ W_lin,
                    const float* __restrict__ b_lin,
                    const float* __restrict__ h0,
                    const float* __restrict__ c0,
                    float* __restrict__ out,
                    int T) {
    __shared__ __align__(16) float hs[2][HD];
    __shared__ float red[8];
    __shared__ __align__(8) u64 mbar[2];

    const int r = threadIdx.x;
    uint32_t rank;
    asm("mov.u32 %0, %%cluster_ctarank;" : "=r"(rank));
    const int q = (int)rank;
    const int peer = 1 - q;
    const int gate = r & 3;           // i,f,g,o interleaved within warp
    const int m    = r >> 2;          // local element 0..63
    const int row  = gate * HD + q * HALF + m;
    const int j    = q * HALF + m;
    const bool prod = (gate == 0);

    // act = out_sc * tanh(in_sc * x) + out_b
    //   sigmoid gates (i,f,o): 0.5*tanh(0.5x)+0.5 ; g gate: tanh(x)
    const float in_sc  = (gate == 2) ? 1.f  : 0.5f;
    const float out_sc = (gate == 2) ? 1.f  : 0.5f;
    const float out_b  = (gate == 2) ? 0.f  : 0.5f;

    const uint32_t mb0 = smem_u32(&mbar[0]);
    const uint32_t mb1 = smem_u32(&mbar[1]);
    const uint32_t peer_mb0 = mapa_u32(mb0, (uint32_t)peer);
    const uint32_t peer_mb1 = mapa_u32(mb1, (uint32_t)peer);
    const uint32_t peer_hs  = mapa_u32(smem_u32(&hs[0][0]), (uint32_t)peer);

    if (r == 0) { mbar_init(mb0, 1); mbar_init(mb1, 1); }

    if (r < HD) hs[0][r] = h0[r];
    float c = prod ? c0[j] : 0.f;

    const float wih  = W_ih[row];
    const float bsum = b_ih[row] + b_hh[row];
    u64 wl[32], wrm[32];
    {
        const u64* wrow = (const u64*)(W_hh + (size_t)row * HD);
        #pragma unroll
        for (int k = 0; k < 32; ++k) wl[k]  = wrow[q * 32 + k];
        #pragma unroll
        for (int k = 0; k < 32; ++k) wrm[k] = wrow[peer * 32 + k];
    }
    __syncthreads();
    if (r == 0) {
        mbar_arrive(mb0);                 // step 0 passes trivially (h0 local)
        mbar_arrive_expect_tx(mb1, 256);  // arm for step 1's incoming half
    }
    __syncthreads();
    cluster_sync();                       // peer barrier init/arm visible

    const int q16 = q * 16, p16 = peer * 16;
    float xt = __ldg(&x[0]);

    for (int t = 0; t < T; ++t) {
        const int b  = t & 1;
        const int nb = b ^ 1;
        const uint32_t mbw = b ? mb1 : mb0;
        const uint32_t pmb = nb ? peer_mb1 : peer_mb0;
        const uint32_t parity = (uint32_t)((t >> 1) & 1);

        const float xnext = __ldg(&x[(t + 1 < T) ? (t + 1) : t]);

        u64 a0 = pack2(fmaf(wih, xt, bsum), 0.f);
        u64 a1 = 0ull, a2 = 0ull, a3 = 0ull;

        const ulonglong2* hv2 = (const ulonglong2*)(&hs[b][0]);

        // local half (independent of peer)
        #pragma unroll
        for (int k = 0; k < 16; k += 2) {
            ulonglong2 u = hv2[q16 + k];
            ulonglong2 v = hv2[q16 + k + 1];
            a0 = ffma2(wl[2 * k + 0], u.x, a0);
            a1 = ffma2(wl[2 * k + 1], u.y, a1);
            a2 = ffma2(wl[2 * k + 2], v.x, a2);
            a3 = ffma2(wl[2 * k + 3], v.y, a3);
        }

        mbar_wait(mbw, parity);                       // peer half landed
        if (r == 0) mbar_arrive_expect_tx(mbw, 256);  // re-arm for step t+2

        #pragma unroll
        for (int k = 0; k < 16; k += 2) {
            ulonglong2 u = hv2[p16 + k];
            ulonglong2 v = hv2[p16 + k + 1];
            a0 = ffma2(wrm[2 * k + 0], u.x, a0);
            a1 = ffma2(wrm[2 * k + 1], u.y, a1);
            a2 = ffma2(wrm[2 * k + 2], v.x, a2);
            a3 = ffma2(wrm[2 * k + 3], v.y, a3);
        }

        // packed combine: (a0+a1) + (a2+a3), then one scalar add
        const u64 sv = addf2(addf2(a0, a1), addf2(a2, a3));
        float slo, shi;
        unpack2(sv, slo, shi);
        const float gpre = slo + shi;

        // MUFU tanh-based activation
        const float act = fmaf(out_sc, tanhfast(in_sc * gpre), out_b);

        const float fv = __shfl_xor_sync(0xFFFFFFFFu, act, 1);
        const float gv = __shfl_xor_sync(0xFFFFFFFFu, act, 2);
        const float ov = __shfl_xor_sync(0xFFFFFFFFu, act, 3);

        if (prod) {
            c = fmaf(fv, c, act * gv);           // act == i on producer lane
            const float hnew = ov * tanhfast(c);
            const uint32_t off = (uint32_t)((nb * HD + j) * 4);
            st_async_f32(peer_hs + off, hnew, pmb);  // remote first
            hs[nb][j] = hnew;
        }
        __syncthreads();
        xt = xnext;
    }

    // CTA0 consumes final h
    if (q == 0) {
        const uint32_t mbw = (T & 1) ? mb1 : mb0;
        mbar_wait(mbw, (uint32_t)((T >> 1) & 1));
        const int bf = T & 1;
        float v = (r < HD) ? hs[bf][r] * W_lin[r] : 0.f;
        #pragma unroll
        for (int o = 16; o > 0; o >>= 1)
            v += __shfl_down_sync(0xFFFFFFFFu, v, o);
        if ((r & 31) == 0) red[r >> 5] = v;
        __syncthreads();
        if (r == 0) out[0] = red[0] + red[1] + red[2] + red[3] + b_lin[0];
    }
    cluster_sync();   // peer must outlive CTA0's final consumption
}

extern "C" void kernel_launch(void* const* d_in, const int* in_sizes, int n_in,
                              void* d_out, int out_size) {
    const float* x     = (const float*)d_in[0];
    const float* W_ih  = (const float*)d_in[1];
    const float* W_hh  = (const float*)d_in[2];
    const float* b_ih  = (const float*)d_in[3];
    const float* b_hh  = (const float*)d_in[4];
    const float* W_lin = (const float*)d_in[5];
    const float* b_lin = (const float*)d_in[6];
    const float* h0    = (const float*)d_in[7];
    const float* c0    = (const float*)d_in[8];
    float* out = (float*)d_out;

    const int T = in_sizes[0];

    lstm_cluster_kernel<<<2, TPC>>>(x, W_ih, W_hh, b_ih, b_hh,
                                    W_lin, b_lin, h0, c0, out, T);
}